// round 1
// baseline (speedup 1.0000x reference)
#include <cuda_runtime.h>
#include <math.h>

#define BB   4
#define SSQ  1024
#define DD   1024
#define HHN  16
#define DHD  64
#define BHN  64
#define ATT_SCALE 0.03125f   /* 1/sqrt(1024) */

// ---------------- scratch (static __device__, allowed) ----------------
__device__ float g_q [(size_t)BHN * SSQ * DHD];   // 16 MB, head-major [bh][s][dh]
__device__ float g_k [(size_t)BHN * SSQ * DHD];
__device__ float g_w [(size_t)BHN * SSQ * DHD];
__device__ float g_t [(size_t)BHN * SSQ * SSQ];   // 256 MB   (q+v) @ r^T
__device__ float g_ac[(size_t)BHN * SSQ * SSQ];   // 256 MB   (q+u) @ k^T
__device__ float g_rm[BHN * SSQ];                 // row max
__device__ float g_rz[BHN * SSQ];                 // row sum
__device__ float g_o [(size_t)BB * SSQ * DD];     // 16 MB, merged-head [b][s][d]

// =====================================================================
// GEMM: C[m][n] = sum_k A[m][k] * W[n][k] + bias[n]
// M=4096, N=1024, K=1024. 128x128 tile, k-step 16, 8x8 per thread.
// headmajor=1 -> write to [bh][s][dh] layout; else plain [m][n].
// =====================================================================
__global__ __launch_bounds__(256) void gemm_proj(
    const float* __restrict__ A, const float* __restrict__ W,
    const float* __restrict__ bias, float* __restrict__ C, int headmajor)
{
    __shared__ __align__(16) float As[16][132];
    __shared__ __align__(16) float Bs[16][132];

    const int m0 = blockIdx.x * 128;
    const int n0 = blockIdx.y * 128;
    const int t  = threadIdx.x;
    const int lr = t >> 1;          // 0..127 tile row for loads
    const int ls = (t & 1) * 8;     // k sub-segment for loads
    const int tx = t & 15;
    const int ty = t >> 4;

    const float* Ap = A + (size_t)(m0 + lr) * DD + ls;
    const float* Bp = W + (size_t)(n0 + lr) * DD + ls;

    float acc[8][8];
#pragma unroll
    for (int i = 0; i < 8; i++)
#pragma unroll
        for (int j = 0; j < 8; j++) acc[i][j] = 0.f;

    for (int k0 = 0; k0 < DD; k0 += 16) {
        float4 a0 = *(const float4*)(Ap + k0);
        float4 a1 = *(const float4*)(Ap + k0 + 4);
        float4 b0 = *(const float4*)(Bp + k0);
        float4 b1 = *(const float4*)(Bp + k0 + 4);
        __syncthreads();
        As[ls+0][lr]=a0.x; As[ls+1][lr]=a0.y; As[ls+2][lr]=a0.z; As[ls+3][lr]=a0.w;
        As[ls+4][lr]=a1.x; As[ls+5][lr]=a1.y; As[ls+6][lr]=a1.z; As[ls+7][lr]=a1.w;
        Bs[ls+0][lr]=b0.x; Bs[ls+1][lr]=b0.y; Bs[ls+2][lr]=b0.z; Bs[ls+3][lr]=b0.w;
        Bs[ls+4][lr]=b1.x; Bs[ls+5][lr]=b1.y; Bs[ls+6][lr]=b1.z; Bs[ls+7][lr]=b1.w;
        __syncthreads();
#pragma unroll
        for (int kk = 0; kk < 16; kk++) {
            float4 t0 = *(const float4*)&As[kk][ty * 4];
            float4 t1 = *(const float4*)&As[kk][64 + ty * 4];
            float4 t2 = *(const float4*)&Bs[kk][tx * 4];
            float4 t3 = *(const float4*)&Bs[kk][64 + tx * 4];
            float a[8] = {t0.x,t0.y,t0.z,t0.w, t1.x,t1.y,t1.z,t1.w};
            float b[8] = {t2.x,t2.y,t2.z,t2.w, t3.x,t3.y,t3.z,t3.w};
#pragma unroll
            for (int i = 0; i < 8; i++)
#pragma unroll
                for (int j = 0; j < 8; j++)
                    acc[i][j] = fmaf(a[i], b[j], acc[i][j]);
        }
    }

#pragma unroll
    for (int i = 0; i < 8; i++) {
        const int ml   = (i < 4) ? (ty * 4 + i) : (64 + ty * 4 + (i - 4));
        const int grow = m0 + ml;
        const int bb   = grow >> 10;
        const int sI   = grow & 1023;
#pragma unroll
        for (int jg = 0; jg < 2; jg++) {
            const int nl   = jg ? (64 + tx * 4) : (tx * 4);
            const int gcol = n0 + nl;
            float4 vv;
            vv.x = acc[i][jg*4+0] + bias[gcol+0];
            vv.y = acc[i][jg*4+1] + bias[gcol+1];
            vv.z = acc[i][jg*4+2] + bias[gcol+2];
            vv.w = acc[i][jg*4+3] + bias[gcol+3];
            if (headmajor) {
                const int h = gcol >> 6, dd = gcol & 63;
                *(float4*)&C[(((size_t)bb * HHN + h) * SSQ + sI) * DHD + dd] = vv;
            } else {
                *(float4*)&C[(size_t)grow * DD + gcol] = vv;
            }
        }
    }
}

// =====================================================================
// Batched [1024,64]@[64,1024] GEMM:
//   z<64 : ac[bh][j][m] = sum_k (q+u)[bh][j][k] * k[bh][m][k]
//   z>=64: t [bh][j][l] = sum_k (q+v)[bh][j][k] * pos_head[bh][l][k]
// 64x64 tile per block, full K=64, 4x4 per thread.
// =====================================================================
__global__ __launch_bounds__(256) void qkt_kernel(
    const float* __restrict__ q, const float* __restrict__ kmat,
    const float* __restrict__ pos, const float* __restrict__ u,
    const float* __restrict__ v, float* __restrict__ acout,
    float* __restrict__ tout)
{
    __shared__ __align__(16) float As[64][65];
    __shared__ __align__(16) float Bs[64][65];

    const int bh    = blockIdx.z & 63;
    const int which = blockIdx.z >> 6;      // 0 = ac, 1 = t
    const int m0 = blockIdx.x * 64;
    const int j0 = blockIdx.y * 64;
    const int t  = threadIdx.x;
    const int row = t >> 2;
    const int ks  = (t & 3) * 16;
    const float* vec = which ? v : u;

    const float* ap = q + ((size_t)bh * SSQ + j0 + row) * DHD + ks;
    const float* bp;
    if (!which) {
        bp = kmat + ((size_t)bh * SSQ + m0 + row) * DHD + ks;
    } else {
        const int bb = bh >> 4, h = bh & 15;
        bp = pos + ((size_t)bb * SSQ + m0 + row) * DD + h * DHD + ks;
    }
#pragma unroll
    for (int i = 0; i < 4; i++) {
        float4 av = *(const float4*)(ap + i * 4);
        As[row][ks+i*4+0] = av.x + vec[ks+i*4+0];
        As[row][ks+i*4+1] = av.y + vec[ks+i*4+1];
        As[row][ks+i*4+2] = av.z + vec[ks+i*4+2];
        As[row][ks+i*4+3] = av.w + vec[ks+i*4+3];
        float4 bv = *(const float4*)(bp + i * 4);
        Bs[row][ks+i*4+0] = bv.x;
        Bs[row][ks+i*4+1] = bv.y;
        Bs[row][ks+i*4+2] = bv.z;
        Bs[row][ks+i*4+3] = bv.w;
    }
    __syncthreads();

    const int tx = t & 15, ty = t >> 4;
    float acc[4][4] = {};
#pragma unroll 16
    for (int kk = 0; kk < 64; kk++) {
        float a[4], b[4];
#pragma unroll
        for (int i = 0; i < 4; i++) a[i] = As[ty * 4 + i][kk];
#pragma unroll
        for (int j = 0; j < 4; j++) b[j] = Bs[tx * 4 + j][kk];
#pragma unroll
        for (int i = 0; i < 4; i++)
#pragma unroll
            for (int j = 0; j < 4; j++)
                acc[i][j] = fmaf(a[i], b[j], acc[i][j]);
    }

    float* out = which ? tout : acout;
#pragma unroll
    for (int i = 0; i < 4; i++) {
        float4 vv = make_float4(acc[i][0], acc[i][1], acc[i][2], acc[i][3]);
        *(float4*)&out[((size_t)bh * SSQ + j0 + ty * 4 + i) * SSQ + m0 + tx * 4] = vv;
    }
}

// =====================================================================
// Row softmax stats over logits = (ac + shift(t)) * SCALE. One warp/row.
// shift: m<=j -> t[j][m-j+1023]; m==j+1 -> 0; m>j+1 -> t[j+1][m-j-2]
// =====================================================================
__global__ __launch_bounds__(256) void rowstat_kernel(
    const float* __restrict__ acin, const float* __restrict__ tin,
    float* __restrict__ rm, float* __restrict__ rz)
{
    const int gid  = blockIdx.x * 256 + threadIdx.x;
    const int warp = gid >> 5;
    const int lane = threadIdx.x & 31;
    const int bh = warp >> 10;
    const int j  = warp & 1023;
    const float* acrow = acin + ((size_t)bh * SSQ + j) * SSQ;
    const float* trow  = tin  + ((size_t)bh * SSQ + j) * SSQ;

    float mrun = -1e30f, zrun = 0.f;
    for (int mm = lane; mm < SSQ; mm += 32) {
        const int dlt = mm - j;
        float bd;
        if (dlt <= 0)      bd = trow[dlt + 1023];
        else if (dlt == 1) bd = 0.f;
        else               bd = trow[SSQ + dlt - 2];
        const float s = (acrow[mm] + bd) * ATT_SCALE;
        const float nm = fmaxf(mrun, s);
        zrun = zrun * __expf(mrun - nm) + __expf(s - nm);
        mrun = nm;
    }
#pragma unroll
    for (int off = 16; off > 0; off >>= 1) {
        const float om = __shfl_xor_sync(0xffffffffu, mrun, off);
        const float oz = __shfl_xor_sync(0xffffffffu, zrun, off);
        const float nm = fmaxf(mrun, om);
        zrun = zrun * __expf(mrun - nm) + oz * __expf(om - nm);
        mrun = nm;
    }
    if (lane == 0) { rm[warp] = mrun; rz[warp] = zrun; }
}

// =====================================================================
// PV: o[bh][j][:] = (1/Z_j) * sum_m exp(logit[j][m]-max_j) * w[bh][m][:]
// Block = 64 rows x 64 dh of one bh; loop m in 64-chunks; P built on the fly.
// Output written merged-head [b][s][d].
// =====================================================================
__global__ __launch_bounds__(256) void pv_kernel(
    const float* __restrict__ acin, const float* __restrict__ tin,
    const float* __restrict__ wmat, const float* __restrict__ rm,
    const float* __restrict__ rz, float* __restrict__ oout)
{
    __shared__ __align__(16) float Ps[64][65];
    __shared__ __align__(16) float Ws[64][65];

    const int bh = blockIdx.y;
    const int j0 = blockIdx.x * 64;
    const int t  = threadIdx.x;
    const int row = t >> 2;
    const int ks  = (t & 3) * 16;
    const int tx = t & 15, ty = t >> 4;
    const int j = j0 + row;

    const float rmax = rm[bh * SSQ + j];
    const float* acrow = acin + ((size_t)bh * SSQ + j) * SSQ;
    const float* trow  = tin  + ((size_t)bh * SSQ + j) * SSQ;

    float acc[4][4] = {};
    for (int m0 = 0; m0 < SSQ; m0 += 64) {
        __syncthreads();
#pragma unroll
        for (int ii = 0; ii < 16; ii++) {
            const int mm = m0 + ks + ii;
            const int dlt = mm - j;
            float bd;
            if (dlt <= 0)      bd = trow[dlt + 1023];
            else if (dlt == 1) bd = 0.f;
            else               bd = trow[SSQ + dlt - 2];
            Ps[row][ks + ii] = __expf((acrow[mm] + bd) * ATT_SCALE - rmax);
        }
        const float* wp = wmat + ((size_t)bh * SSQ + m0 + row) * DHD + ks;
#pragma unroll
        for (int i = 0; i < 4; i++) {
            float4 wv = *(const float4*)(wp + i * 4);
            Ws[row][ks+i*4+0] = wv.x;
            Ws[row][ks+i*4+1] = wv.y;
            Ws[row][ks+i*4+2] = wv.z;
            Ws[row][ks+i*4+3] = wv.w;
        }
        __syncthreads();
#pragma unroll 16
        for (int kk = 0; kk < 64; kk++) {
            float a[4], b[4];
#pragma unroll
            for (int i = 0; i < 4; i++) a[i] = Ps[ty * 4 + i][kk];
#pragma unroll
            for (int jj = 0; jj < 4; jj++) b[jj] = Ws[kk][tx * 4 + jj];
#pragma unroll
            for (int i = 0; i < 4; i++)
#pragma unroll
                for (int jj = 0; jj < 4; jj++)
                    acc[i][jj] = fmaf(a[i], b[jj], acc[i][jj]);
        }
    }

    const int bb = bh >> 4, h = bh & 15;
#pragma unroll
    for (int i = 0; i < 4; i++) {
        const int jr = j0 + ty * 4 + i;
        const float inv = 1.0f / rz[bh * SSQ + jr];
        float4 vv = make_float4(acc[i][0]*inv, acc[i][1]*inv, acc[i][2]*inv, acc[i][3]*inv);
        *(float4*)&oout[((size_t)bb * SSQ + jr) * DD + h * DHD + tx * 4] = vv;
    }
}

// =====================================================================
extern "C" void kernel_launch(void* const* d_in, const int* in_sizes, int n_in,
                              void* d_out, int out_size)
{
    const float* x   = (const float*)d_in[0];
    const float* u   = (const float*)d_in[1];
    const float* v   = (const float*)d_in[2];
    const float* pos = (const float*)d_in[3];
    const float* Wq  = (const float*)d_in[4];
    const float* bq  = (const float*)d_in[5];
    const float* Wk  = (const float*)d_in[6];
    const float* bk  = (const float*)d_in[7];
    const float* Wv  = (const float*)d_in[8];
    const float* bv  = (const float*)d_in[9];
    const float* Wc  = (const float*)d_in[10];
    const float* bc  = (const float*)d_in[11];
    float* out = (float*)d_out;

    float *q, *k, *w, *tb, *ac, *rmp, *rzp, *ob;
    cudaGetSymbolAddress((void**)&q,   g_q);
    cudaGetSymbolAddress((void**)&k,   g_k);
    cudaGetSymbolAddress((void**)&w,   g_w);
    cudaGetSymbolAddress((void**)&tb,  g_t);
    cudaGetSymbolAddress((void**)&ac,  g_ac);
    cudaGetSymbolAddress((void**)&rmp, g_rm);
    cudaGetSymbolAddress((void**)&rzp, g_rz);
    cudaGetSymbolAddress((void**)&ob,  g_o);

    dim3 gproj(32, 8);   // M/128, N/128
    gemm_proj<<<gproj, 256>>>(x, Wq, bq, q, 1);
    gemm_proj<<<gproj, 256>>>(x, Wk, bk, k, 1);
    gemm_proj<<<gproj, 256>>>(x, Wv, bv, w, 1);

    qkt_kernel<<<dim3(16, 16, 128), 256>>>(q, k, pos, u, v, ac, tb);

    rowstat_kernel<<<8192, 256>>>(ac, tb, rmp, rzp);

    pv_kernel<<<dim3(16, 64), 256>>>(ac, tb, w, rmp, rzp, ob);

    gemm_proj<<<gproj, 256>>>(ob, Wc, bc, out, 0);
}

// round 3
// speedup vs baseline: 1.6745x; 1.6745x over previous
#include <cuda_runtime.h>
#include <cuda_bf16.h>
#include <cstdint>
#include <math.h>

#define SSQ  1024
#define DD   1024
#define HHN  16
#define DHD  64
#define BHN  64
#define MTOT 4096
#define ATT_SCALE 0.03125f

// ---------------- fp32 scratch ----------------
__device__ float g_t [(size_t)BHN * SSQ * SSQ];   // 256 MB
__device__ float g_ac[(size_t)BHN * SSQ * SSQ];   // 256 MB
__device__ float g_w [(size_t)BHN * SSQ * DHD];   // 16 MB head-major fp32
__device__ float g_o [(size_t)MTOT * DD];         // 16 MB merged-head fp32
__device__ float g_rm[BHN * SSQ];
__device__ float g_rz[BHN * SSQ];

// ---------------- bf16 pool ----------------
#define NX   ((size_t)MTOT * DD)
#define NW   ((size_t)DD * DD)
#define NH   ((size_t)BHN * SSQ * DHD)
#define O_XH  ((size_t)0)
#define O_XL  (O_XH + NX)
#define O_WQH (O_XL + NX)
#define O_WQL (O_WQH + NW)
#define O_WKH (O_WQL + NW)
#define O_WKL (O_WKH + NW)
#define O_WVH (O_WKL + NW)
#define O_WVL (O_WVH + NW)
#define O_WCH (O_WVL + NW)
#define O_WCL (O_WCH + NW)
#define O_QUH (O_WCL + NW)
#define O_QUL (O_QUH + NH)
#define O_QVH (O_QUL + NH)
#define O_QVL (O_QVH + NH)
#define O_KHH (O_QVL + NH)
#define O_KHL (O_KHH + NH)
#define O_RHH (O_KHL + NH)
#define O_RHL (O_RHH + NH)
#define O_OBH (O_RHL + NH)
#define O_OBL (O_OBH + NX)
#define BF_TOTAL (O_OBL + NX)
__device__ __align__(16) __nv_bfloat16 g_bf[BF_TOTAL];

// ================= helpers =================
__device__ __forceinline__ uint32_t smem_u32(const void* p) {
    uint32_t a;
    asm("{ .reg .u64 t; cvta.to.shared.u64 t, %1; cvt.u32.u64 %0, t; }" : "=r"(a) : "l"(p));
    return a;
}
__device__ __forceinline__ void split2(float v, __nv_bfloat16& h, __nv_bfloat16& l) {
    h = __float2bfloat16(v);
    l = __float2bfloat16(v - __bfloat162float(h));
}
__device__ __forceinline__ void cp16(uint32_t dst, const void* src) {
    asm volatile("cp.async.cg.shared.global [%0], [%1], 16;" :: "r"(dst), "l"(src));
}
__device__ __forceinline__ void cp_commit() { asm volatile("cp.async.commit_group;"); }
__device__ __forceinline__ void ldsm4(uint32_t& r0, uint32_t& r1, uint32_t& r2, uint32_t& r3,
                                      uint32_t addr) {
    asm volatile("ldmatrix.sync.aligned.m8n8.x4.shared.b16 {%0,%1,%2,%3}, [%4];"
                 : "=r"(r0), "=r"(r1), "=r"(r2), "=r"(r3) : "r"(addr));
}
__device__ __forceinline__ void mma_bf16(float* d, const uint32_t* a, const uint32_t* b) {
    asm volatile(
        "mma.sync.aligned.m16n8k16.row.col.f32.bf16.bf16.f32 "
        "{%0,%1,%2,%3}, {%4,%5,%6,%7}, {%8,%9}, {%0,%1,%2,%3};"
        : "+f"(d[0]), "+f"(d[1]), "+f"(d[2]), "+f"(d[3])
        : "r"(a[0]), "r"(a[1]), "r"(a[2]), "r"(a[3]), "r"(b[0]), "r"(b[1]));
}
// 16B-chunk XOR swizzle: row r, chunk c (0..3), 64B rows
__device__ __forceinline__ uint32_t swadr(uint32_t tb, int r, int c) {
    return tb + r * 64 + (((c ^ ((r >> 1) & 3))) << 4);
}

// stage layout: Ah +0, Al +8192, Bh +16384, Bl +24576 ; stage size 32768
#define STAGE_SZ 32768
#define SMEM_BYTES (2 * STAGE_SZ)

// load one stage: 4 tiles of 128 rows x 32 bf16 cols
__device__ __forceinline__ void stage_load(
    uint32_t sb, const __nv_bfloat16* Ah, const __nv_bfloat16* Al,
    const __nv_bfloat16* Bh, const __nv_bfloat16* Bl,
    int arow0, int brow0, int ldA, int ldB, int k0, int tid)
{
#pragma unroll
    for (int half = 0; half < 2; half++) {
        const int q = half * 256 + tid;       // 0..511
        const int r = q >> 2, c = q & 3;
        const int kel = k0 + c * 8;
        cp16(swadr(sb,          r, c), Ah + (size_t)(arow0 + r) * ldA + kel);
        cp16(swadr(sb +  8192,  r, c), Al + (size_t)(arow0 + r) * ldA + kel);
        cp16(swadr(sb + 16384,  r, c), Bh + (size_t)(brow0 + r) * ldB + kel);
        cp16(swadr(sb + 24576,  r, c), Bl + (size_t)(brow0 + r) * ldB + kel);
    }
}

__device__ __forceinline__ void compute_chunk(uint32_t sb, int wm, int wn, int lane,
                                              float acc[4][4][4])
{
    const uint32_t Ahb = sb, Alb = sb + 8192, Bhb = sb + 16384, Blb = sb + 24576;
#pragma unroll
    for (int kk = 0; kk < 2; kk++) {
        uint32_t ah[4][4], al[4][4], bh[4][2], bl[4][2];
        const int ar = wm * 64 + (lane & 15);
        const int ac = 2 * kk + (lane >> 4);
#pragma unroll
        for (int i = 0; i < 4; i++) {
            ldsm4(ah[i][0], ah[i][1], ah[i][2], ah[i][3], swadr(Ahb, ar + i * 16, ac));
            ldsm4(al[i][0], al[i][1], al[i][2], al[i][3], swadr(Alb, ar + i * 16, ac));
        }
        const int br = wn * 32 + (lane & 7) + ((lane >> 4) << 3);
        const int bc = 2 * kk + ((lane >> 3) & 1);
#pragma unroll
        for (int p = 0; p < 2; p++) {
            uint32_t t0, t1, t2, t3;
            ldsm4(t0, t1, t2, t3, swadr(Bhb, br + p * 16, bc));
            bh[2*p][0] = t0; bh[2*p][1] = t1; bh[2*p+1][0] = t2; bh[2*p+1][1] = t3;
            ldsm4(t0, t1, t2, t3, swadr(Blb, br + p * 16, bc));
            bl[2*p][0] = t0; bl[2*p][1] = t1; bl[2*p+1][0] = t2; bl[2*p+1][1] = t3;
        }
#pragma unroll
        for (int i = 0; i < 4; i++)
#pragma unroll
            for (int j = 0; j < 4; j++) {
                mma_bf16(acc[i][j], ah[i], bh[j]);
                mma_bf16(acc[i][j], ah[i], bl[j]);
                mma_bf16(acc[i][j], al[i], bh[j]);
            }
    }
}

// ================= conversion kernels =================
__global__ __launch_bounds__(256) void conv_split(
    const float* __restrict__ s, __nv_bfloat16* __restrict__ h,
    __nv_bfloat16* __restrict__ l, int n)
{
    int i = blockIdx.x * 256 + threadIdx.x;
    if (i < n) {
        __nv_bfloat16 hh, ll; split2(s[i], hh, ll);
        h[i] = hh; l[i] = ll;
    }
}

__global__ __launch_bounds__(256) void conv_pos(
    const float* __restrict__ pos, __nv_bfloat16* __restrict__ h,
    __nv_bfloat16* __restrict__ l)
{
    int d = blockIdx.x * 256 + threadIdx.x;
    int bh = d >> 16;
    int s  = (d >> 6) & 1023;
    int dd = d & 63;
    int b = bh >> 4, hh_ = bh & 15;
    float v = pos[(((size_t)b << 10) + s) * 1024 + (hh_ << 6) + dd];
    __nv_bfloat16 hb, lb; split2(v, hb, lb);
    h[d] = hb; l[d] = lb;
}

// ================= projection GEMM (mma.sync) =================
// C[m][n] = sum_k A[m][k]*B[n][k] + bias[n];  M=4096, N=1024, K=1024
// mode 0: fp32 [m][n];  1: (c+u)->o1,(c+v)->o2 bf16 hi/lo head-major;
// mode 2: c->o1 bf16 head-major;  3: c->fp32 head-major
__global__ __launch_bounds__(256, 1) void mm_gemm(
    const __nv_bfloat16* __restrict__ Ah, const __nv_bfloat16* __restrict__ Al,
    const __nv_bfloat16* __restrict__ Bh, const __nv_bfloat16* __restrict__ Bl,
    const float* __restrict__ bias, const float* __restrict__ uvec,
    const float* __restrict__ vvec, int mode, float* __restrict__ out_f,
    __nv_bfloat16* __restrict__ o1h, __nv_bfloat16* __restrict__ o1l,
    __nv_bfloat16* __restrict__ o2h, __nv_bfloat16* __restrict__ o2l)
{
    extern __shared__ __align__(16) char smem[];
    const uint32_t sb0 = smem_u32(smem);
    const int tid = threadIdx.x, lane = tid & 31, w = tid >> 5;
    const int wm = w >> 2, wn = w & 3;
    const int m0 = blockIdx.x * 128, n0 = blockIdx.y * 128;

    float acc[4][4][4];
#pragma unroll
    for (int i = 0; i < 4; i++)
#pragma unroll
        for (int j = 0; j < 4; j++)
#pragma unroll
            for (int q = 0; q < 4; q++) acc[i][j][q] = 0.f;

    const int NC = DD / 32;
    stage_load(sb0, Ah, Al, Bh, Bl, m0, n0, DD, DD, 0, tid);
    cp_commit();
    for (int c = 0; c < NC; c++) {
        if (c + 1 < NC) {
            stage_load(sb0 + ((c + 1) & 1) * STAGE_SZ, Ah, Al, Bh, Bl,
                       m0, n0, DD, DD, (c + 1) * 32, tid);
            cp_commit();
            asm volatile("cp.async.wait_group 1;");
        } else {
            asm volatile("cp.async.wait_group 0;");
        }
        __syncthreads();
        compute_chunk(sb0 + (c & 1) * STAGE_SZ, wm, wn, lane, acc);
        __syncthreads();
    }

    const int g = lane >> 2, t2 = (lane & 3) * 2;
#pragma unroll
    for (int i = 0; i < 4; i++) {
#pragma unroll
        for (int j = 0; j < 4; j++) {
#pragma unroll
            for (int half = 0; half < 2; half++) {
                const int grow = m0 + wm * 64 + i * 16 + g + half * 8;
                const int gcol = n0 + wn * 32 + j * 8 + t2;
                float v0 = acc[i][j][half * 2 + 0] + bias[gcol];
                float v1 = acc[i][j][half * 2 + 1] + bias[gcol + 1];
                if (mode == 0) {
                    *(float2*)&out_f[(size_t)grow * DD + gcol] = make_float2(v0, v1);
                } else {
                    const int b = grow >> 10, s = grow & 1023;
                    const int h = gcol >> 6, dd = gcol & 63;
                    const size_t base = (((size_t)(b * HHN + h) << 10) + s) * DHD + dd;
                    if (mode == 3) {
                        *(float2*)&out_f[base] = make_float2(v0, v1);
                    } else if (mode == 2) {
                        __nv_bfloat16 h0, l0, h1, l1;
                        split2(v0, h0, l0); split2(v1, h1, l1);
                        *(__nv_bfloat162*)&o1h[base] = __nv_bfloat162(h0, h1);
                        *(__nv_bfloat162*)&o1l[base] = __nv_bfloat162(l0, l1);
                    } else {
                        __nv_bfloat16 h0, l0, h1, l1;
                        split2(v0 + uvec[dd], h0, l0); split2(v1 + uvec[dd + 1], h1, l1);
                        *(__nv_bfloat162*)&o1h[base] = __nv_bfloat162(h0, h1);
                        *(__nv_bfloat162*)&o1l[base] = __nv_bfloat162(l0, l1);
                        split2(v0 + vvec[dd], h0, l0); split2(v1 + vvec[dd + 1], h1, l1);
                        *(__nv_bfloat162*)&o2h[base] = __nv_bfloat162(h0, h1);
                        *(__nv_bfloat162*)&o2l[base] = __nv_bfloat162(l0, l1);
                    }
                }
            }
        }
    }
}

// ================= batched QK^T / QR^T (mma.sync, K=64) =================
__global__ __launch_bounds__(256, 1) void mm_qkt(
    const __nv_bfloat16* __restrict__ quh, const __nv_bfloat16* __restrict__ qul,
    const __nv_bfloat16* __restrict__ qvh, const __nv_bfloat16* __restrict__ qvl,
    const __nv_bfloat16* __restrict__ khh, const __nv_bfloat16* __restrict__ khl,
    const __nv_bfloat16* __restrict__ rhh, const __nv_bfloat16* __restrict__ rhl,
    float* __restrict__ acout, float* __restrict__ tout)
{
    extern __shared__ __align__(16) char smem[];
    const uint32_t sb0 = smem_u32(smem);
    const int tid = threadIdx.x, lane = tid & 31, w = tid >> 5;
    const int wm = w >> 2, wn = w & 3;
    const int bh = blockIdx.z & 63;
    const int which = blockIdx.z >> 6;
    const int m0 = blockIdx.x * 128;   // cols
    const int j0 = blockIdx.y * 128;   // rows

    const __nv_bfloat16* Ah = (which ? qvh : quh) + (size_t)bh * SSQ * DHD;
    const __nv_bfloat16* Al = (which ? qvl : qul) + (size_t)bh * SSQ * DHD;
    const __nv_bfloat16* Bh = (which ? rhh : khh) + (size_t)bh * SSQ * DHD;
    const __nv_bfloat16* Bl = (which ? rhl : khl) + (size_t)bh * SSQ * DHD;

    float acc[4][4][4];
#pragma unroll
    for (int i = 0; i < 4; i++)
#pragma unroll
        for (int j = 0; j < 4; j++)
#pragma unroll
            for (int q = 0; q < 4; q++) acc[i][j][q] = 0.f;

    stage_load(sb0, Ah, Al, Bh, Bl, j0, m0, DHD, DHD, 0, tid);
    cp_commit();
    for (int c = 0; c < 2; c++) {
        if (c == 0) {
            stage_load(sb0 + STAGE_SZ, Ah, Al, Bh, Bl, j0, m0, DHD, DHD, 32, tid);
            cp_commit();
            asm volatile("cp.async.wait_group 1;");
        } else {
            asm volatile("cp.async.wait_group 0;");
        }
        __syncthreads();
        compute_chunk(sb0 + c * STAGE_SZ, wm, wn, lane, acc);
        __syncthreads();
    }

    float* out = (which ? tout : acout) + (size_t)bh * SSQ * SSQ;
    const int g = lane >> 2, t2 = (lane & 3) * 2;
#pragma unroll
    for (int i = 0; i < 4; i++)
#pragma unroll
        for (int j = 0; j < 4; j++)
#pragma unroll
            for (int half = 0; half < 2; half++) {
                const int grow = j0 + wm * 64 + i * 16 + g + half * 8;
                const int gcol = m0 + wn * 32 + j * 8 + t2;
                *(float2*)&out[(size_t)grow * SSQ + gcol] =
                    make_float2(acc[i][j][half * 2], acc[i][j][half * 2 + 1]);
            }
}

// ================= softmax row stats =================
__global__ __launch_bounds__(256) void rowstat_kernel(
    const float* __restrict__ acin, const float* __restrict__ tin,
    float* __restrict__ rm, float* __restrict__ rz)
{
    const int gid  = blockIdx.x * 256 + threadIdx.x;
    const int warp = gid >> 5;
    const int lane = threadIdx.x & 31;
    const int bh = warp >> 10;
    const int j  = warp & 1023;
    const float* acrow = acin + ((size_t)bh * SSQ + j) * SSQ;
    const float* trow  = tin  + ((size_t)bh * SSQ + j) * SSQ;

    float mrun = -1e30f, zrun = 0.f;
    for (int mm = lane; mm < SSQ; mm += 32) {
        const int dlt = mm - j;
        float bd;
        if (dlt <= 0)      bd = trow[dlt + 1023];
        else if (dlt == 1) bd = 0.f;
        else               bd = trow[SSQ + dlt - 2];
        const float s = (acrow[mm] + bd) * ATT_SCALE;
        const float nm = fmaxf(mrun, s);
        zrun = zrun * __expf(mrun - nm) + __expf(s - nm);
        mrun = nm;
    }
#pragma unroll
    for (int off = 16; off > 0; off >>= 1) {
        const float om = __shfl_xor_sync(0xffffffffu, mrun, off);
        const float oz = __shfl_xor_sync(0xffffffffu, zrun, off);
        const float nm = fmaxf(mrun, om);
        zrun = zrun * __expf(mrun - nm) + oz * __expf(om - nm);
        mrun = nm;
    }
    if (lane == 0) { rm[warp] = mrun; rz[warp] = zrun; }
}

// ================= PV =================
__global__ __launch_bounds__(256) void pv_kernel(
    const float* __restrict__ acin, const float* __restrict__ tin,
    const float* __restrict__ wmat, const float* __restrict__ rm,
    const float* __restrict__ rz, float* __restrict__ oout)
{
    __shared__ __align__(16) float Ps[64][65];
    __shared__ __align__(16) float Ws[64][65];

    const int bh = blockIdx.y;
    const int j0 = blockIdx.x * 64;
    const int t  = threadIdx.x;
    const int row = t >> 2;
    const int ks  = (t & 3) * 16;
    const int tx = t & 15, ty = t >> 4;
    const int j = j0 + row;

    const float rmax = rm[bh * SSQ + j];
    const float* acrow = acin + ((size_t)bh * SSQ + j) * SSQ;
    const float* trow  = tin  + ((size_t)bh * SSQ + j) * SSQ;

    float acc[4][4] = {};
    for (int m0 = 0; m0 < SSQ; m0 += 64) {
        __syncthreads();
#pragma unroll
        for (int ii = 0; ii < 16; ii++) {
            const int mm = m0 + ks + ii;
            const int dlt = mm - j;
            float bd;
            if (dlt <= 0)      bd = trow[dlt + 1023];
            else if (dlt == 1) bd = 0.f;
            else               bd = trow[SSQ + dlt - 2];
            Ps[row][ks + ii] = __expf((acrow[mm] + bd) * ATT_SCALE - rmax);
        }
        const float* wp = wmat + ((size_t)bh * SSQ + m0 + row) * DHD + ks;
#pragma unroll
        for (int i = 0; i < 4; i++) {
            float4 wv = *(const float4*)(wp + i * 4);
            Ws[row][ks+i*4+0] = wv.x;
            Ws[row][ks+i*4+1] = wv.y;
            Ws[row][ks+i*4+2] = wv.z;
            Ws[row][ks+i*4+3] = wv.w;
        }
        __syncthreads();
#pragma unroll 16
        for (int kk = 0; kk < 64; kk++) {
            float a[4], b[4];
#pragma unroll
            for (int i = 0; i < 4; i++) a[i] = Ps[ty * 4 + i][kk];
#pragma unroll
            for (int jj = 0; jj < 4; jj++) b[jj] = Ws[kk][tx * 4 + jj];
#pragma unroll
            for (int i = 0; i < 4; i++)
#pragma unroll
                for (int jj = 0; jj < 4; jj++)
                    acc[i][jj] = fmaf(a[i], b[jj], acc[i][jj]);
        }
    }

    const int bb = bh >> 4, h = bh & 15;
#pragma unroll
    for (int i = 0; i < 4; i++) {
        const int jr = j0 + ty * 4 + i;
        const float inv = 1.0f / rz[bh * SSQ + jr];
        float4 vv = make_float4(acc[i][0]*inv, acc[i][1]*inv, acc[i][2]*inv, acc[i][3]*inv);
        *(float4*)&oout[((size_t)bb * SSQ + jr) * DD + h * DHD + tx * 4] = vv;
    }
}

// =====================================================================
extern "C" void kernel_launch(void* const* d_in, const int* in_sizes, int n_in,
                              void* d_out, int out_size)
{
    const float* x   = (const float*)d_in[0];
    const float* u   = (const float*)d_in[1];
    const float* v   = (const float*)d_in[2];
    const float* pos = (const float*)d_in[3];
    const float* Wq  = (const float*)d_in[4];
    const float* bq  = (const float*)d_in[5];
    const float* Wk  = (const float*)d_in[6];
    const float* bk  = (const float*)d_in[7];
    const float* Wv  = (const float*)d_in[8];
    const float* bv  = (const float*)d_in[9];
    const float* Wc  = (const float*)d_in[10];
    const float* bc  = (const float*)d_in[11];
    float* out = (float*)d_out;

    float *tb, *ac, *wf, *ob, *rmp, *rzp;
    __nv_bfloat16* bf;
    cudaGetSymbolAddress((void**)&tb,  g_t);
    cudaGetSymbolAddress((void**)&ac,  g_ac);
    cudaGetSymbolAddress((void**)&wf,  g_w);
    cudaGetSymbolAddress((void**)&ob,  g_o);
    cudaGetSymbolAddress((void**)&rmp, g_rm);
    cudaGetSymbolAddress((void**)&rzp, g_rz);
    cudaGetSymbolAddress((void**)&bf,  g_bf);

    cudaFuncSetAttribute(mm_gemm, cudaFuncAttributeMaxDynamicSharedMemorySize, SMEM_BYTES);
    cudaFuncSetAttribute(mm_qkt,  cudaFuncAttributeMaxDynamicSharedMemorySize, SMEM_BYTES);

    conv_split<<<(int)((NX + 255) / 256), 256>>>(x,  bf + O_XH,  bf + O_XL,  (int)NX);
    conv_split<<<(int)((NW + 255) / 256), 256>>>(Wq, bf + O_WQH, bf + O_WQL, (int)NW);
    conv_split<<<(int)((NW + 255) / 256), 256>>>(Wk, bf + O_WKH, bf + O_WKL, (int)NW);
    conv_split<<<(int)((NW + 255) / 256), 256>>>(Wv, bf + O_WVH, bf + O_WVL, (int)NW);
    conv_split<<<(int)((NW + 255) / 256), 256>>>(Wc, bf + O_WCH, bf + O_WCL, (int)NW);
    conv_pos  <<<(int)((NH + 255) / 256), 256>>>(pos, bf + O_RHH, bf + O_RHL);

    dim3 gp(32, 8);
    mm_gemm<<<gp, 256, SMEM_BYTES>>>(bf + O_XH, bf + O_XL, bf + O_WQH, bf + O_WQL,
        bq, u, v, 1, nullptr,
        bf + O_QUH, bf + O_QUL, bf + O_QVH, bf + O_QVL);
    mm_gemm<<<gp, 256, SMEM_BYTES>>>(bf + O_XH, bf + O_XL, bf + O_WKH, bf + O_WKL,
        bk, u, v, 2, nullptr,
        bf + O_KHH, bf + O_KHL, nullptr, nullptr);
    mm_gemm<<<gp, 256, SMEM_BYTES>>>(bf + O_XH, bf + O_XL, bf + O_WVH, bf + O_WVL,
        bv, u, v, 3, wf, nullptr, nullptr, nullptr, nullptr);

    mm_qkt<<<dim3(8, 8, 128), 256, SMEM_BYTES>>>(
        bf + O_QUH, bf + O_QUL, bf + O_QVH, bf + O_QVL,
        bf + O_KHH, bf + O_KHL, bf + O_RHH, bf + O_RHL, ac, tb);

    rowstat_kernel<<<8192, 256>>>(ac, tb, rmp, rzp);
    pv_kernel<<<dim3(16, 64), 256>>>(ac, tb, wf, rmp, rzp, ob);

    conv_split<<<(int)((NX + 255) / 256), 256>>>(ob, bf + O_OBH, bf + O_OBL, (int)NX);
    mm_gemm<<<gp, 256, SMEM_BYTES>>>(bf + O_OBH, bf + O_OBL, bf + O_WCH, bf + O_WCL,
        bc, u, v, 0, out, nullptr, nullptr, nullptr, nullptr);
}